// round 1
// baseline (speedup 1.0000x reference)
#include <cuda_runtime.h>
#include <math.h>

// Problem constants
#define C 256            // channels / protos spatial count
#define HW 65536         // 256*256 pixels
#define NPROTO 256
#define BM 64            // pixel tile per block in main GEMM
#define KC 16            // K chunk

// Scratch (device globals: no allocation allowed)
__device__ float g_X[C * C];        // X[c][p]  pooled sup_x
__device__ float g_XT[C * C];       // XT[p][c] transpose
__device__ float g_coef[C * 3];     // tridiagonal (A*cal) coefficients per row
__device__ float g_sel[C];          // selection mask (1/0) per proto
__device__ float g_qscale[HW];      // 1 / max(||qry_pix||, 1e-4)
__device__ float g_protoT[C * C];   // protoT[c][n] = 20 * Xn[c][n]/max(norm_n,1e-4)

// ---------------------------------------------------------------------------
// K1: avg-pool sup_x (per channel) and sup_y. blockIdx.x in [0,256]; 256 thr.
// thread tid -> pooled cell (ph, pw)
// ---------------------------------------------------------------------------
__global__ void pool_kernel(const float* __restrict__ sup_x,
                            const float* __restrict__ sup_y) {
    const int bc = blockIdx.x;
    const int tid = threadIdx.x;
    const int ph = tid >> 4;
    const int pw = tid & 15;
    const float* src = (bc < C) ? (sup_x + (size_t)bc * HW) : sup_y;
    const float* base = src + ph * 16 * 256 + pw * 16;
    float s = 0.f;
#pragma unroll
    for (int r = 0; r < 16; ++r) {
        const float4* row = (const float4*)(base + r * 256);
        float4 a = row[0], b = row[1], c = row[2], d = row[3];
        s += (a.x + a.y + a.z + a.w) + (b.x + b.y + b.z + b.w)
           + (c.x + c.y + c.z + c.w) + (d.x + d.y + d.z + d.w);
    }
    s *= (1.0f / 256.0f);
    if (bc < C) {
        g_X[bc * C + tid]  = s;
        g_XT[tid * C + bc] = s;
    } else {
        g_sel[tid] = (s > 0.5f) ? 1.0f : 0.0f;
    }
}

// ---------------------------------------------------------------------------
// K2: per-pixel inverse norm of qry (over channels). 256 blocks x 256 thr.
// ---------------------------------------------------------------------------
__global__ void qnorm_kernel(const float* __restrict__ qry) {
    const int pix = blockIdx.x * 256 + threadIdx.x;
    float s = 0.f;
#pragma unroll 8
    for (int c = 0; c < C; ++c) {
        float v = qry[(size_t)c * HW + pix];
        s += v * v;
    }
    g_qscale[pix] = 1.0f / fmaxf(sqrtf(s), 1e-4f);
}

// ---------------------------------------------------------------------------
// K3: w1 row i = X[i]·X[j]^T, row softmax, band coefficients (A*cal).
// grid 256 (row i), 256 threads (col j).
// ---------------------------------------------------------------------------
__global__ void w1_kernel(const float* __restrict__ cal) {
    __shared__ float Xi[C];
    __shared__ float red[C];
    const int i = blockIdx.x;
    const int j = threadIdx.x;

    Xi[j] = g_X[i * C + j];
    __syncthreads();

    float dot = 0.f;
#pragma unroll 8
    for (int p = 0; p < C; ++p)
        dot += Xi[p] * g_XT[p * C + j];   // coalesced across j

    // block max
    red[j] = dot;
    __syncthreads();
    for (int s2 = 128; s2 > 0; s2 >>= 1) {
        if (j < s2) red[j] = fmaxf(red[j], red[j + s2]);
        __syncthreads();
    }
    const float mx = red[0];
    __syncthreads();

    // block sum of exp
    float e = expf(dot - mx);
    red[j] = e;
    __syncthreads();
    for (int s2 = 128; s2 > 0; s2 >>= 1) {
        if (j < s2) red[j] += red[j + s2];
        __syncthreads();
    }
    const float denom = red[0];

    if (j >= i - 1 && j <= i + 1) {
        float soft = expf(dot - mx) / denom;
        float a = (1.0f + 0.2f * soft) * cal[i * C + j];
        g_coef[i * 3 + (j - i + 1)] = a;
    }
    // edges never written above -> force zero (determinism across replays)
    if (i == 0 && j == 0)      g_coef[0] = 0.f;
    if (i == C - 1 && j == C - 1) g_coef[(C - 1) * 3 + 2] = 0.f;
}

// ---------------------------------------------------------------------------
// K4: Xn (3-pt stencil) + per-proto normalization; writes protoT[c][n] with
// the *20 folded in. grid 256 (proto n = pooled p), 256 threads (channel i).
// ---------------------------------------------------------------------------
__global__ void proto_kernel() {
    __shared__ float red[C];
    const int p = blockIdx.x;
    const int i = threadIdx.x;

    const float c0 = g_coef[i * 3 + 0];
    const float c1 = g_coef[i * 3 + 1];
    const float c2 = g_coef[i * 3 + 2];
    const float xm1 = (i > 0)     ? g_XT[p * C + i - 1] : 0.f;
    const float x0  =               g_XT[p * C + i];
    const float xp1 = (i < C - 1) ? g_XT[p * C + i + 1] : 0.f;
    const float xn = c0 * xm1 + c1 * x0 + c2 * xp1;

    red[i] = xn * xn;
    __syncthreads();
    for (int s2 = 128; s2 > 0; s2 >>= 1) {
        if (i < s2) red[i] += red[i + s2];
        __syncthreads();
    }
    const float scale = 20.0f / fmaxf(sqrtf(red[0]), 1e-4f);
    g_protoT[i * C + p] = xn * scale;
}

// ---------------------------------------------------------------------------
// K5: fused GEMM (65536x256x256) + masked softmax + weighted sum + argmax.
// Block: 256 threads, tile BM=64 pixels x 256 protos.
// Thread (mg = tid/32, ng = tid%32) computes 8x8 microtile:
//   pixels m0+mg*8 .. +7, protos ng*8 .. +7.
// Epilogue: warp mg owns all 256 protos of its 8 pixels -> shuffle reduce.
// ---------------------------------------------------------------------------
__global__ __launch_bounds__(256) void gemm_epi_kernel(
    const float* __restrict__ qry, float* __restrict__ out) {
    __shared__ __align__(16) float Qs[KC][BM];
    __shared__ __align__(16) float Ps[KC][NPROTO];

    const int tid = threadIdx.x;
    const int m0 = blockIdx.x * BM;
    const int mg = tid >> 5;
    const int ng = tid & 31;

    float acc[8][8];
#pragma unroll
    for (int i = 0; i < 8; ++i)
#pragma unroll
        for (int j = 0; j < 8; ++j) acc[i][j] = 0.f;

    const int lc = tid >> 4;          // k-row this thread loads
    const int lm = (tid & 15) * 4;    // Qs column (4 floats)
    const int ln = (tid & 15) * 16;   // Ps column (16 floats)

    for (int kt = 0; kt < C; kt += KC) {
        // load Q tile (16 x 64) and P tile (16 x 256), coalesced float4
        *(float4*)&Qs[lc][lm] =
            *(const float4*)(qry + (size_t)(kt + lc) * HW + m0 + lm);
        const float* pp = g_protoT + (kt + lc) * NPROTO + ln;
        *(float4*)&Ps[lc][ln + 0]  = *(const float4*)(pp + 0);
        *(float4*)&Ps[lc][ln + 4]  = *(const float4*)(pp + 4);
        *(float4*)&Ps[lc][ln + 8]  = *(const float4*)(pp + 8);
        *(float4*)&Ps[lc][ln + 12] = *(const float4*)(pp + 12);
        __syncthreads();

#pragma unroll
        for (int k = 0; k < KC; ++k) {
            float4 qa = *(const float4*)&Qs[k][mg * 8];
            float4 qb = *(const float4*)&Qs[k][mg * 8 + 4];
            float4 pa = *(const float4*)&Ps[k][ng * 8];
            float4 pb = *(const float4*)&Ps[k][ng * 8 + 4];
            float qr[8] = {qa.x, qa.y, qa.z, qa.w, qb.x, qb.y, qb.z, qb.w};
            float pr[8] = {pa.x, pa.y, pa.z, pa.w, pb.x, pb.y, pb.z, pb.w};
#pragma unroll
            for (int i = 0; i < 8; ++i)
#pragma unroll
                for (int j = 0; j < 8; ++j)
                    acc[i][j] += qr[i] * pr[j];
        }
        __syncthreads();
    }

    // ---- fused epilogue (per warp; lane owns protos ng*8..ng*8+7) ----
    float sel8[8];
#pragma unroll
    for (int j = 0; j < 8; ++j) sel8[j] = g_sel[ng * 8 + j];

    const int mbase = m0 + mg * 8;
#pragma unroll
    for (int i = 0; i < 8; ++i) {
        const float sc = g_qscale[mbase + i];
        float mv[8];
        float bestv = -3.0e38f;
        int bestn = 0;
#pragma unroll
        for (int j = 0; j < 8; ++j) {
            mv[j] = (sel8[j] > 0.5f) ? acc[i][j] * sc : -1.0e9f;
            if (mv[j] > bestv) { bestv = mv[j]; bestn = ng * 8 + j; }
        }
        // warp max (tie -> lowest index, matching jnp.argmax first-occurrence)
#pragma unroll
        for (int off = 16; off > 0; off >>= 1) {
            float ov = __shfl_xor_sync(0xFFFFFFFFu, bestv, off);
            int on   = __shfl_xor_sync(0xFFFFFFFFu, bestn, off);
            if (ov > bestv || (ov == bestv && on < bestn)) { bestv = ov; bestn = on; }
        }
        float se = 0.f, sd = 0.f;
#pragma unroll
        for (int j = 0; j < 8; ++j) {
            float e = expf(mv[j] - bestv);   // -1e9 entries underflow to 0
            se += e;
            sd += e * mv[j];
        }
#pragma unroll
        for (int off = 16; off > 0; off >>= 1) {
            se += __shfl_xor_sync(0xFFFFFFFFu, se, off);
            sd += __shfl_xor_sync(0xFFFFFFFFu, sd, off);
        }
        if (ng == 0) {
            out[mbase + i]      = sd / se;        // pred_grid
            out[HW + mbase + i] = (float)bestn;   // debug_assign
        }
    }
}

// ---------------------------------------------------------------------------
// Inputs (metadata order): qry f32[16777216], sup_x f32[16777216],
// sup_y f32[65536], s_init_seed i32[200] (unused), cal f32[65536]
// Output: f32[131072] = pred_grid(65536) ++ debug_assign(65536)
// ---------------------------------------------------------------------------
extern "C" void kernel_launch(void* const* d_in, const int* in_sizes, int n_in,
                              void* d_out, int out_size) {
    const float* qry   = (const float*)d_in[0];
    const float* sup_x = (const float*)d_in[1];
    const float* sup_y = (const float*)d_in[2];
    const float* cal   = (const float*)d_in[4];
    float* out = (float*)d_out;

    pool_kernel<<<C + 1, 256>>>(sup_x, sup_y);
    qnorm_kernel<<<HW / 256, 256>>>(qry);
    w1_kernel<<<C, 256>>>(cal);
    proto_kernel<<<C, 256>>>();
    gemm_epi_kernel<<<HW / BM, 256>>>(qry, out);
}

// round 2
// speedup vs baseline: 1.0323x; 1.0323x over previous
#include <cuda_runtime.h>
#include <math.h>
#include <stdint.h>

// Problem constants
#define C 256            // channels / protos spatial count
#define HW 65536         // 256*256 pixels
#define NPROTO 256
#define BM 64            // pixel tile per block in main GEMM
#define KC 16            // K chunk

// Scratch (device globals: no allocation allowed)
__device__ float g_X[C * C];        // X[c][p]  pooled sup_x
__device__ float g_XT[C * C];       // XT[p][c] transpose
__device__ float g_coef[C * 3];     // tridiagonal (A*cal) coefficients per row
__device__ float g_sel[C];          // selection mask (1/0) per proto
__device__ float g_qscale[HW];      // 1 / max(||qry_pix||, 1e-4)
__device__ float g_protoT[C * C];   // protoT[c][n] = 20 * Xn[c][n]/max(norm_n,1e-4)

__device__ __forceinline__ void fma2(uint64_t& d, uint64_t a, uint64_t b) {
    asm("fma.rn.f32x2 %0, %1, %2, %0;" : "+l"(d) : "l"(a), "l"(b));
}
__device__ __forceinline__ void unpack2(uint64_t v, float& lo, float& hi) {
    asm("mov.b64 {%0, %1}, %2;" : "=f"(lo), "=f"(hi) : "l"(v));
}

// ---------------------------------------------------------------------------
// K1: avg-pool sup_x (per channel) and sup_y. blockIdx.x in [0,256]; 256 thr.
// ---------------------------------------------------------------------------
__global__ void pool_kernel(const float* __restrict__ sup_x,
                            const float* __restrict__ sup_y) {
    const int bc = blockIdx.x;
    const int tid = threadIdx.x;
    const int ph = tid >> 4;
    const int pw = tid & 15;
    const float* src = (bc < C) ? (sup_x + (size_t)bc * HW) : sup_y;
    const float* base = src + ph * 16 * 256 + pw * 16;
    float s = 0.f;
#pragma unroll
    for (int r = 0; r < 16; ++r) {
        const float4* row = (const float4*)(base + r * 256);
        float4 a = row[0], b = row[1], c = row[2], d = row[3];
        s += (a.x + a.y + a.z + a.w) + (b.x + b.y + b.z + b.w)
           + (c.x + c.y + c.z + c.w) + (d.x + d.y + d.z + d.w);
    }
    s *= (1.0f / 256.0f);
    if (bc < C) {
        g_X[bc * C + tid]  = s;
        g_XT[tid * C + bc] = s;
    } else {
        g_sel[tid] = (s > 0.5f) ? 1.0f : 0.0f;
    }
}

// ---------------------------------------------------------------------------
// K2: per-pixel inverse norm of qry (over channels).
// ---------------------------------------------------------------------------
__global__ void qnorm_kernel(const float* __restrict__ qry) {
    const int pix = blockIdx.x * 256 + threadIdx.x;
    float s = 0.f;
#pragma unroll 8
    for (int c = 0; c < C; ++c) {
        float v = qry[(size_t)c * HW + pix];
        s += v * v;
    }
    g_qscale[pix] = 1.0f / fmaxf(sqrtf(s), 1e-4f);
}

// ---------------------------------------------------------------------------
// K3: w1 row i = X[i]·X[j]^T, row softmax, band coefficients (A*cal).
// ---------------------------------------------------------------------------
__global__ void w1_kernel(const float* __restrict__ cal) {
    __shared__ float Xi[C];
    __shared__ float red[C];
    const int i = blockIdx.x;
    const int j = threadIdx.x;

    Xi[j] = g_X[i * C + j];
    __syncthreads();

    float dot = 0.f;
#pragma unroll 8
    for (int p = 0; p < C; ++p)
        dot += Xi[p] * g_XT[p * C + j];

    red[j] = dot;
    __syncthreads();
    for (int s2 = 128; s2 > 0; s2 >>= 1) {
        if (j < s2) red[j] = fmaxf(red[j], red[j + s2]);
        __syncthreads();
    }
    const float mx = red[0];
    __syncthreads();

    float e = expf(dot - mx);
    red[j] = e;
    __syncthreads();
    for (int s2 = 128; s2 > 0; s2 >>= 1) {
        if (j < s2) red[j] += red[j + s2];
        __syncthreads();
    }
    const float denom = red[0];

    if (j >= i - 1 && j <= i + 1) {
        float soft = expf(dot - mx) / denom;
        float a = (1.0f + 0.2f * soft) * cal[i * C + j];
        g_coef[i * 3 + (j - i + 1)] = a;
    }
    if (i == 0 && j == 0)         g_coef[0] = 0.f;
    if (i == C - 1 && j == C - 1) g_coef[(C - 1) * 3 + 2] = 0.f;
}

// ---------------------------------------------------------------------------
// K4: Xn (3-pt stencil) + per-proto normalization; *20 folded in.
// ---------------------------------------------------------------------------
__global__ void proto_kernel() {
    __shared__ float red[C];
    const int p = blockIdx.x;
    const int i = threadIdx.x;

    const float c0 = g_coef[i * 3 + 0];
    const float c1 = g_coef[i * 3 + 1];
    const float c2 = g_coef[i * 3 + 2];
    const float xm1 = (i > 0)     ? g_XT[p * C + i - 1] : 0.f;
    const float x0  =               g_XT[p * C + i];
    const float xp1 = (i < C - 1) ? g_XT[p * C + i + 1] : 0.f;
    const float xn = c0 * xm1 + c1 * x0 + c2 * xp1;

    red[i] = xn * xn;
    __syncthreads();
    for (int s2 = 128; s2 > 0; s2 >>= 1) {
        if (i < s2) red[i] += red[i + s2];
        __syncthreads();
    }
    const float scale = 20.0f / fmaxf(sqrtf(red[0]), 1e-4f);
    g_protoT[i * C + p] = xn * scale;
}

// ---------------------------------------------------------------------------
// K5: fused GEMM (65536x256x256) + masked softmax + weighted sum + argmax.
// Packed fma.rn.f32x2 inner loop (2 fp32 FMA / inst, bit-exact vs scalar).
// Block: 256 threads, tile BM=64 pixels x 256 protos.
// Thread (mg = tid/32, ng = tid%32):
//   pixels m0 + mg*8 .. +7
//   proto pairs {2*ng + 64*j, 2*ng+1 + 64*j}, j = 0..3  (8 protos)
// Q tile stored duplicated ({q,q} pairs) -> broadcast LDS.64 gives packed
// multiplier directly. P pairs via conflict-free strided LDS.64.
// ---------------------------------------------------------------------------
__global__ __launch_bounds__(256) void gemm_epi_kernel(
    const float* __restrict__ qry, float* __restrict__ out) {
    __shared__ __align__(16) float Qd[KC][BM * 2];    // duplicated pairs
    __shared__ __align__(16) float Ps[KC][NPROTO];

    const int tid = threadIdx.x;
    const int m0 = blockIdx.x * BM;
    const int mg = tid >> 5;
    const int ng = tid & 31;

    uint64_t acc[8][4];
#pragma unroll
    for (int i = 0; i < 8; ++i)
#pragma unroll
        for (int j = 0; j < 4; ++j) acc[i][j] = 0ull;

    const int lc = tid >> 4;          // k-row this thread loads
    const int lm = (tid & 15) * 4;    // source pixel offset (4 floats)
    const int ln = (tid & 15) * 16;   // Ps column (16 floats)

    for (int kt = 0; kt < C; kt += KC) {
        // Q: load 4 floats, store duplicated {x,x,y,y,z,z,w,w}
        float4 v = *(const float4*)(qry + (size_t)(kt + lc) * HW + m0 + lm);
        float4 d0 = make_float4(v.x, v.x, v.y, v.y);
        float4 d1 = make_float4(v.z, v.z, v.w, v.w);
        *(float4*)&Qd[lc][lm * 2]     = d0;
        *(float4*)&Qd[lc][lm * 2 + 4] = d1;
        // P tile (16 x 256)
        const float* pp = g_protoT + (kt + lc) * NPROTO + ln;
        *(float4*)&Ps[lc][ln + 0]  = *(const float4*)(pp + 0);
        *(float4*)&Ps[lc][ln + 4]  = *(const float4*)(pp + 4);
        *(float4*)&Ps[lc][ln + 8]  = *(const float4*)(pp + 8);
        *(float4*)&Ps[lc][ln + 12] = *(const float4*)(pp + 12);
        __syncthreads();

#pragma unroll
        for (int k = 0; k < KC; ++k) {
            uint64_t q[8];
#pragma unroll
            for (int i = 0; i < 8; ++i)
                q[i] = *(const uint64_t*)&Qd[k][(mg * 8 + i) * 2];  // broadcast
            uint64_t p[4];
#pragma unroll
            for (int j = 0; j < 4; ++j)
                p[j] = *(const uint64_t*)&Ps[k][2 * ng + 64 * j];   // conflict-free
#pragma unroll
            for (int i = 0; i < 8; ++i)
#pragma unroll
                for (int j = 0; j < 4; ++j)
                    fma2(acc[i][j], q[i], p[j]);
        }
        __syncthreads();
    }

    // ---- fused epilogue (warp mg owns all 256 protos of its 8 pixels) ----
    float sel8[8];
#pragma unroll
    for (int j = 0; j < 4; ++j) {
        sel8[2 * j]     = g_sel[2 * ng + 64 * j];
        sel8[2 * j + 1] = g_sel[2 * ng + 1 + 64 * j];
    }

    const int mbase = m0 + mg * 8;
#pragma unroll
    for (int i = 0; i < 8; ++i) {
        const float sc = g_qscale[mbase + i];
        float mv[8];
        float bestv = -3.0e38f;
        int bestn = 0x7FFFFFFF;
#pragma unroll
        for (int j = 0; j < 4; ++j) {
            float lo, hi;
            unpack2(acc[i][j], lo, hi);
            const int n0 = 2 * ng + 64 * j;
            mv[2 * j]     = (sel8[2 * j]     > 0.5f) ? lo * sc : -1.0e9f;
            mv[2 * j + 1] = (sel8[2 * j + 1] > 0.5f) ? hi * sc : -1.0e9f;
            if (mv[2 * j] > bestv || (mv[2 * j] == bestv && n0 < bestn)) {
                bestv = mv[2 * j]; bestn = n0;
            }
            if (mv[2 * j + 1] > bestv || (mv[2 * j + 1] == bestv && n0 + 1 < bestn)) {
                bestv = mv[2 * j + 1]; bestn = n0 + 1;
            }
        }
        // warp max (tie -> lowest index, matching jnp.argmax first-occurrence)
#pragma unroll
        for (int off = 16; off > 0; off >>= 1) {
            float ov = __shfl_xor_sync(0xFFFFFFFFu, bestv, off);
            int on   = __shfl_xor_sync(0xFFFFFFFFu, bestn, off);
            if (ov > bestv || (ov == bestv && on < bestn)) { bestv = ov; bestn = on; }
        }
        float se = 0.f, sd = 0.f;
#pragma unroll
        for (int j = 0; j < 8; ++j) {
            float e = expf(mv[j] - bestv);   // -1e9 entries underflow to 0
            se += e;
            sd += e * mv[j];
        }
#pragma unroll
        for (int off = 16; off > 0; off >>= 1) {
            se += __shfl_xor_sync(0xFFFFFFFFu, se, off);
            sd += __shfl_xor_sync(0xFFFFFFFFu, sd, off);
        }
        if (ng == 0) {
            out[mbase + i]      = sd / se;        // pred_grid
            out[HW + mbase + i] = (float)bestn;   // debug_assign
        }
    }
}

// ---------------------------------------------------------------------------
// Inputs (metadata order): qry f32[16777216], sup_x f32[16777216],
// sup_y f32[65536], s_init_seed i32[200] (unused), cal f32[65536]
// Output: f32[131072] = pred_grid(65536) ++ debug_assign(65536)
// ---------------------------------------------------------------------------
extern "C" void kernel_launch(void* const* d_in, const int* in_sizes, int n_in,
                              void* d_out, int out_size) {
    const float* qry   = (const float*)d_in[0];
    const float* sup_x = (const float*)d_in[1];
    const float* sup_y = (const float*)d_in[2];
    const float* cal   = (const float*)d_in[4];
    float* out = (float*)d_out;

    pool_kernel<<<C + 1, 256>>>(sup_x, sup_y);
    qnorm_kernel<<<HW / 256, 256>>>(qry);
    w1_kernel<<<C, 256>>>(cal);
    proto_kernel<<<C, 256>>>();
    gemm_epi_kernel<<<HW / BM, 256>>>(qry, out);
}

// round 3
// speedup vs baseline: 1.0333x; 1.0010x over previous
#include <cuda_runtime.h>
#include <math.h>
#include <stdint.h>

// Problem constants
#define C 256            // channels / protos spatial count
#define HW 65536         // 256*256 pixels
#define NPROTO 256
#define BM 64            // pixel tile per block in main GEMM
#define KC 16            // K chunk

// Scratch (device globals: no allocation allowed)
__device__ float g_X[C * C];        // X[c][p]  pooled sup_x
__device__ float g_XT[C * C];       // XT[p][c] transpose
__device__ float g_coef[C * 3];     // tridiagonal (A*cal) coefficients per row
__device__ float g_sel[C];          // selection mask (1/0) per proto
__device__ float g_qscale[HW];      // 1 / max(||qry_pix||, 1e-4)
__device__ float g_protoT[C * C];   // protoT[c][n] = 20 * Xn[c][n]/max(norm_n,1e-4)

__device__ __forceinline__ void fma2(uint64_t& d, uint64_t a, uint64_t b) {
    asm("fma.rn.f32x2 %0, %1, %2, %0;" : "+l"(d) : "l"(a), "l"(b));
}
__device__ __forceinline__ void unpack2(uint64_t v, float& lo, float& hi) {
    asm("mov.b64 {%0, %1}, %2;" : "=f"(lo), "=f"(hi) : "l"(v));
}

// ---------------------------------------------------------------------------
// K1: avg-pool sup_x (per channel) and sup_y. blockIdx.x in [0,256]; 256 thr.
// ---------------------------------------------------------------------------
__global__ void pool_kernel(const float* __restrict__ sup_x,
                            const float* __restrict__ sup_y) {
    const int bc = blockIdx.x;
    const int tid = threadIdx.x;
    const int ph = tid >> 4;
    const int pw = tid & 15;
    const float* src = (bc < C) ? (sup_x + (size_t)bc * HW) : sup_y;
    const float* base = src + ph * 16 * 256 + pw * 16;
    float s = 0.f;
#pragma unroll
    for (int r = 0; r < 16; ++r) {
        const float4* row = (const float4*)(base + r * 256);
        float4 a = row[0], b = row[1], c = row[2], d = row[3];
        s += (a.x + a.y + a.z + a.w) + (b.x + b.y + b.z + b.w)
           + (c.x + c.y + c.z + c.w) + (d.x + d.y + d.z + d.w);
    }
    s *= (1.0f / 256.0f);
    if (bc < C) {
        g_X[bc * C + tid]  = s;
        g_XT[tid * C + bc] = s;
    } else {
        g_sel[tid] = (s > 0.5f) ? 1.0f : 0.0f;
    }
}

// ---------------------------------------------------------------------------
// K2: per-pixel inverse norm of qry (over channels).
// ---------------------------------------------------------------------------
__global__ void qnorm_kernel(const float* __restrict__ qry) {
    const int pix = blockIdx.x * 256 + threadIdx.x;
    float s = 0.f;
#pragma unroll 8
    for (int c = 0; c < C; ++c) {
        float v = qry[(size_t)c * HW + pix];
        s += v * v;
    }
    g_qscale[pix] = 1.0f / fmaxf(sqrtf(s), 1e-4f);
}

// ---------------------------------------------------------------------------
// K3: w1 row i = X[i]·X[j]^T, row softmax, band coefficients (A*cal).
// ---------------------------------------------------------------------------
__global__ void w1_kernel(const float* __restrict__ cal) {
    __shared__ float Xi[C];
    __shared__ float red[C];
    const int i = blockIdx.x;
    const int j = threadIdx.x;

    Xi[j] = g_X[i * C + j];
    __syncthreads();

    float dot = 0.f;
#pragma unroll 8
    for (int p = 0; p < C; ++p)
        dot += Xi[p] * g_XT[p * C + j];

    red[j] = dot;
    __syncthreads();
    for (int s2 = 128; s2 > 0; s2 >>= 1) {
        if (j < s2) red[j] = fmaxf(red[j], red[j + s2]);
        __syncthreads();
    }
    const float mx = red[0];
    __syncthreads();

    float e = expf(dot - mx);
    red[j] = e;
    __syncthreads();
    for (int s2 = 128; s2 > 0; s2 >>= 1) {
        if (j < s2) red[j] += red[j + s2];
        __syncthreads();
    }
    const float denom = red[0];

    if (j >= i - 1 && j <= i + 1) {
        float soft = expf(dot - mx) / denom;
        float a = (1.0f + 0.2f * soft) * cal[i * C + j];
        g_coef[i * 3 + (j - i + 1)] = a;
    }
    if (i == 0 && j == 0)         g_coef[0] = 0.f;
    if (i == C - 1 && j == C - 1) g_coef[(C - 1) * 3 + 2] = 0.f;
}

// ---------------------------------------------------------------------------
// K4: Xn (3-pt stencil) + per-proto normalization; *20 folded in.
// ---------------------------------------------------------------------------
__global__ void proto_kernel() {
    __shared__ float red[C];
    const int p = blockIdx.x;
    const int i = threadIdx.x;

    const float c0 = g_coef[i * 3 + 0];
    const float c1 = g_coef[i * 3 + 1];
    const float c2 = g_coef[i * 3 + 2];
    const float xm1 = (i > 0)     ? g_XT[p * C + i - 1] : 0.f;
    const float x0  =               g_XT[p * C + i];
    const float xp1 = (i < C - 1) ? g_XT[p * C + i + 1] : 0.f;
    const float xn = c0 * xm1 + c1 * x0 + c2 * xp1;

    red[i] = xn * xn;
    __syncthreads();
    for (int s2 = 128; s2 > 0; s2 >>= 1) {
        if (i < s2) red[i] += red[i + s2];
        __syncthreads();
    }
    const float scale = 20.0f / fmaxf(sqrtf(red[0]), 1e-4f);
    g_protoT[i * C + p] = xn * scale;
}

// ---------------------------------------------------------------------------
// K5: fused GEMM (65536x256x256) + masked softmax + weighted sum + argmax.
// Packed fma.rn.f32x2 inner loop (2 fp32 FMA / inst, bit-exact vs scalar).
// Block: 256 threads, tile BM=64 pixels x 256 protos.
// Thread (mg = tid/32, ng = tid%32):
//   pixels m0 + mg*8 .. +7
//   proto pairs {2*ng + 64*j, 2*ng+1 + 64*j}, j = 0..3  (8 protos)
// Q tile stored duplicated ({q,q} pairs) -> broadcast LDS.64 gives packed
// multiplier directly. P pairs via conflict-free strided LDS.64.
// ---------------------------------------------------------------------------
__global__ __launch_bounds__(256) void gemm_epi_kernel(
    const float* __restrict__ qry, float* __restrict__ out) {
    __shared__ __align__(16) float Qd[KC][BM * 2];    // duplicated pairs
    __shared__ __align__(16) float Ps[KC][NPROTO];

    const int tid = threadIdx.x;
    const int m0 = blockIdx.x * BM;
    const int mg = tid >> 5;
    const int ng = tid & 31;

    uint64_t acc[8][4];
#pragma unroll
    for (int i = 0; i < 8; ++i)
#pragma unroll
        for (int j = 0; j < 4; ++j) acc[i][j] = 0ull;

    const int lc = tid >> 4;          // k-row this thread loads
    const int lm = (tid & 15) * 4;    // source pixel offset (4 floats)
    const int ln = (tid & 15) * 16;   // Ps column (16 floats)

    for (int kt = 0; kt < C; kt += KC) {
        // Q: load 4 floats, store duplicated {x,x,y,y,z,z,w,w}
        float4 v = *(const float4*)(qry + (size_t)(kt + lc) * HW + m0 + lm);
        float4 d0 = make_float4(v.x, v.x, v.y, v.y);
        float4 d1 = make_float4(v.z, v.z, v.w, v.w);
        *(float4*)&Qd[lc][lm * 2]     = d0;
        *(float4*)&Qd[lc][lm * 2 + 4] = d1;
        // P tile (16 x 256)
        const float* pp = g_protoT + (kt + lc) * NPROTO + ln;
        *(float4*)&Ps[lc][ln + 0]  = *(const float4*)(pp + 0);
        *(float4*)&Ps[lc][ln + 4]  = *(const float4*)(pp + 4);
        *(float4*)&Ps[lc][ln + 8]  = *(const float4*)(pp + 8);
        *(float4*)&Ps[lc][ln + 12] = *(const float4*)(pp + 12);
        __syncthreads();

#pragma unroll
        for (int k = 0; k < KC; ++k) {
            uint64_t q[8];
#pragma unroll
            for (int i = 0; i < 8; ++i)
                q[i] = *(const uint64_t*)&Qd[k][(mg * 8 + i) * 2];  // broadcast
            uint64_t p[4];
#pragma unroll
            for (int j = 0; j < 4; ++j)
                p[j] = *(const uint64_t*)&Ps[k][2 * ng + 64 * j];   // conflict-free
#pragma unroll
            for (int i = 0; i < 8; ++i)
#pragma unroll
                for (int j = 0; j < 4; ++j)
                    fma2(acc[i][j], q[i], p[j]);
        }
        __syncthreads();
    }

    // ---- fused epilogue (warp mg owns all 256 protos of its 8 pixels) ----
    float sel8[8];
#pragma unroll
    for (int j = 0; j < 4; ++j) {
        sel8[2 * j]     = g_sel[2 * ng + 64 * j];
        sel8[2 * j + 1] = g_sel[2 * ng + 1 + 64 * j];
    }

    const int mbase = m0 + mg * 8;
#pragma unroll
    for (int i = 0; i < 8; ++i) {
        const float sc = g_qscale[mbase + i];
        float mv[8];
        float bestv = -3.0e38f;
        int bestn = 0x7FFFFFFF;
#pragma unroll
        for (int j = 0; j < 4; ++j) {
            float lo, hi;
            unpack2(acc[i][j], lo, hi);
            const int n0 = 2 * ng + 64 * j;
            mv[2 * j]     = (sel8[2 * j]     > 0.5f) ? lo * sc : -1.0e9f;
            mv[2 * j + 1] = (sel8[2 * j + 1] > 0.5f) ? hi * sc : -1.0e9f;
            if (mv[2 * j] > bestv || (mv[2 * j] == bestv && n0 < bestn)) {
                bestv = mv[2 * j]; bestn = n0;
            }
            if (mv[2 * j + 1] > bestv || (mv[2 * j + 1] == bestv && n0 + 1 < bestn)) {
                bestv = mv[2 * j + 1]; bestn = n0 + 1;
            }
        }
        // warp max (tie -> lowest index, matching jnp.argmax first-occurrence)
#pragma unroll
        for (int off = 16; off > 0; off >>= 1) {
            float ov = __shfl_xor_sync(0xFFFFFFFFu, bestv, off);
            int on   = __shfl_xor_sync(0xFFFFFFFFu, bestn, off);
            if (ov > bestv || (ov == bestv && on < bestn)) { bestv = ov; bestn = on; }
        }
        float se = 0.f, sd = 0.f;
#pragma unroll
        for (int j = 0; j < 8; ++j) {
            float e = expf(mv[j] - bestv);   // -1e9 entries underflow to 0
            se += e;
            sd += e * mv[j];
        }
#pragma unroll
        for (int off = 16; off > 0; off >>= 1) {
            se += __shfl_xor_sync(0xFFFFFFFFu, se, off);
            sd += __shfl_xor_sync(0xFFFFFFFFu, sd, off);
        }
        if (ng == 0) {
            out[mbase + i]      = sd / se;        // pred_grid
            out[HW + mbase + i] = (float)bestn;   // debug_assign
        }
    }
}

// ---------------------------------------------------------------------------
// Inputs (metadata order): qry f32[16777216], sup_x f32[16777216],
// sup_y f32[65536], s_init_seed i32[200] (unused), cal f32[65536]
// Output: f32[131072] = pred_grid(65536) ++ debug_assign(65536)
// ---------------------------------------------------------------------------
extern "C" void kernel_launch(void* const* d_in, const int* in_sizes, int n_in,
                              void* d_out, int out_size) {
    const float* qry   = (const float*)d_in[0];
    const float* sup_x = (const float*)d_in[1];
    const float* sup_y = (const float*)d_in[2];
    const float* cal   = (const float*)d_in[4];
    float* out = (float*)d_out;

    pool_kernel<<<C + 1, 256>>>(sup_x, sup_y);
    qnorm_kernel<<<HW / 256, 256>>>(qry);
    w1_kernel<<<C, 256>>>(cal);
    proto_kernel<<<C, 256>>>();
    gemm_epi_kernel<<<HW / BM, 256>>>(qry, out);
}

// round 8
// speedup vs baseline: 1.4882x; 1.4402x over previous
#include <cuda_runtime.h>
#include <math.h>
#include <stdint.h>

#define C 256
#define HW 65536
#define BMPIX 128          // pixels per CTA
#define NCHUNK 8           // K chunks of 32

__device__ float g_X[C * C];
__device__ float g_XT[C * C];
__device__ float g_coef[C * 3];
__device__ float g_sel[C];
// B pre-packed for mma fragments:
// float4[c][ks][n][kb] = { hi(k), lo(k), hi(k+4), lo(k+4) },  k = c*32+ks*8+kb
__device__ float4 g_bpack[NCHUNK * 4 * 256 * 4];

__device__ __forceinline__ float tf32r(float x) {
    uint32_t u;
    asm("cvt.rna.tf32.f32 %0, %1;" : "=r"(u) : "f"(x));
    return __uint_as_float(u);
}

__device__ __forceinline__ void mma8(float* d, const uint32_t* a,
                                     uint32_t b0, uint32_t b1) {
    asm("mma.sync.aligned.m16n8k8.row.col.f32.tf32.tf32.f32 "
        "{%0,%1,%2,%3}, {%4,%5,%6,%7}, {%8,%9}, {%0,%1,%2,%3};"
        : "+f"(d[0]), "+f"(d[1]), "+f"(d[2]), "+f"(d[3])
        : "r"(a[0]), "r"(a[1]), "r"(a[2]), "r"(a[3]), "r"(b0), "r"(b1));
}

// ---------------------------------------------------------------------------
__global__ void pool_kernel(const float* __restrict__ sup_x,
                            const float* __restrict__ sup_y) {
    const int bc = blockIdx.x, tid = threadIdx.x;
    const int ph = tid >> 4, pw = tid & 15;
    const float* src = (bc < C) ? (sup_x + (size_t)bc * HW) : sup_y;
    const float* base = src + ph * 16 * 256 + pw * 16;
    float s = 0.f;
#pragma unroll
    for (int r = 0; r < 16; ++r) {
        const float4* row = (const float4*)(base + r * 256);
        float4 a = row[0], b = row[1], c = row[2], d = row[3];
        s += (a.x + a.y + a.z + a.w) + (b.x + b.y + b.z + b.w)
           + (c.x + c.y + c.z + c.w) + (d.x + d.y + d.z + d.w);
    }
    s *= (1.0f / 256.0f);
    if (bc < C) { g_X[bc * C + tid] = s; g_XT[tid * C + bc] = s; }
    else        { g_sel[tid] = (s > 0.5f) ? 1.0f : 0.0f; }
}

__global__ void w1_kernel(const float* __restrict__ cal) {
    __shared__ float Xi[C], red[C];
    const int i = blockIdx.x, j = threadIdx.x;
    Xi[j] = g_X[i * C + j];
    __syncthreads();
    float dot = 0.f;
#pragma unroll 8
    for (int p = 0; p < C; ++p) dot += Xi[p] * g_XT[p * C + j];
    red[j] = dot; __syncthreads();
    for (int s = 128; s > 0; s >>= 1) { if (j < s) red[j] = fmaxf(red[j], red[j + s]); __syncthreads(); }
    const float mx = red[0]; __syncthreads();
    red[j] = expf(dot - mx); __syncthreads();
    for (int s = 128; s > 0; s >>= 1) { if (j < s) red[j] += red[j + s]; __syncthreads(); }
    const float denom = red[0];
    if (j >= i - 1 && j <= i + 1)
        g_coef[i * 3 + (j - i + 1)] = (1.0f + 0.2f * expf(dot - mx) / denom) * cal[i * C + j];
    if (i == 0 && j == 0)         g_coef[0] = 0.f;
    if (i == C - 1 && j == C - 1) g_coef[(C - 1) * 3 + 2] = 0.f;
}

// proto values -> packed tf32 hi/lo fragment layout
__global__ void proto_kernel() {
    __shared__ float red[C];
    const int p = blockIdx.x, i = threadIdx.x;   // p = proto, i = channel
    const float c0 = g_coef[i * 3], c1 = g_coef[i * 3 + 1], c2 = g_coef[i * 3 + 2];
    const float xm1 = (i > 0) ? g_XT[p * C + i - 1] : 0.f;
    const float x0 = g_XT[p * C + i];
    const float xp1 = (i < C - 1) ? g_XT[p * C + i + 1] : 0.f;
    const float xn = c0 * xm1 + c1 * x0 + c2 * xp1;
    red[i] = xn * xn; __syncthreads();
    for (int s = 128; s > 0; s >>= 1) { if (i < s) red[i] += red[i + s]; __syncthreads(); }
    const float v = xn * (20.0f / fmaxf(sqrtf(red[0]), 1e-4f));
    const float h = tf32r(v);
    const float l = tf32r(v - h);
    const int c = i >> 5, ks = (i >> 3) & 3, klow = i & 7;
    const int kb = klow & 3, h4 = klow >> 2;
    float* dst = (float*)&g_bpack[c * 4096 + ((ks * 256 + p) << 2) + kb];
    dst[h4 * 2]     = h;
    dst[h4 * 2 + 1] = l;
}

// ---------------------------------------------------------------------------
// mma.sync tf32 3-term GEMM (M=128/block, N=256, K=256) + fused epilogue.
// 8 warps: widM = wid&3 (32 pixels each), widN = wid>>2 (128 protos each).
// ---------------------------------------------------------------------------
#define SM_SEL  65536
#define SM_CSE  66560
#define SM_CSD  67072
#define SM_CBV  67584
#define SM_CBN  68096
#define SMEM_BYTES 68608

__global__ __launch_bounds__(256, 1) void gemm_mma_kernel(
    const float* __restrict__ qry, float* __restrict__ out) {
    extern __shared__ char sm[];
    float4* bsm = (float4*)sm;                       // 64KB: [ks][n][kb]
    float* sel_s = (float*)(sm + SM_SEL);

    const int tid = threadIdx.x, wid = tid >> 5, lane = tid & 31;
    const int lq = lane >> 2, lk = lane & 3;
    const int widM = wid & 3, widN = wid >> 2;
    const int m0 = blockIdx.x * BMPIX;

    sel_s[tid] = g_sel[tid];

    float acc[2][16][4];
#pragma unroll
    for (int mt = 0; mt < 2; ++mt)
#pragma unroll
        for (int nt = 0; nt < 16; ++nt)
#pragma unroll
            for (int q = 0; q < 4; ++q) acc[mt][nt][q] = 0.f;
    float nrm[2][2] = {{0.f, 0.f}, {0.f, 0.f}};

    const float* qbase = qry + m0 + widM * 32 + lq;

    for (int c = 0; c < NCHUNK; ++c) {
        __syncthreads();
        {
            const float4* src = g_bpack + c * 4096;
#pragma unroll
            for (int t = 0; t < 16; ++t)
                bsm[t * 256 + tid] = src[t * 256 + tid];
        }
        __syncthreads();
#pragma unroll
        for (int ks = 0; ks < 4; ++ks) {
            const int k0 = c * 32 + ks * 8;
            const float* q0 = qbase + (size_t)(k0 + lk) * HW;
            const float* q4 = q0 + (size_t)4 * HW;
            uint32_t ah[2][4], al[2][4];
#pragma unroll
            for (int mt = 0; mt < 2; ++mt) {
                float v0 = q0[mt * 16], v1 = q0[mt * 16 + 8];
                float v2 = q4[mt * 16], v3 = q4[mt * 16 + 8];
                nrm[mt][0] += v0 * v0 + v2 * v2;
                nrm[mt][1] += v1 * v1 + v3 * v3;
                float h0 = tf32r(v0), h1 = tf32r(v1), h2 = tf32r(v2), h3 = tf32r(v3);
                ah[mt][0] = __float_as_uint(h0);
                ah[mt][1] = __float_as_uint(h1);
                ah[mt][2] = __float_as_uint(h2);
                ah[mt][3] = __float_as_uint(h3);
                al[mt][0] = __float_as_uint(tf32r(v0 - h0));
                al[mt][1] = __float_as_uint(tf32r(v1 - h1));
                al[mt][2] = __float_as_uint(tf32r(v2 - h2));
                al[mt][3] = __float_as_uint(tf32r(v3 - h3));
            }
            const float4* bp = bsm + ks * 1024 + widN * 512 + lq * 4 + lk;
#pragma unroll
            for (int nt = 0; nt < 16; ++nt) {
                float4 b = bp[nt * 32];
                uint32_t bh0 = __float_as_uint(b.x), bl0 = __float_as_uint(b.y);
                uint32_t bh1 = __float_as_uint(b.z), bl1 = __float_as_uint(b.w);
                mma8(acc[0][nt], ah[0], bh0, bh1);
                mma8(acc[1][nt], ah[1], bh0, bh1);
                mma8(acc[0][nt], al[0], bh0, bh1);
                mma8(acc[1][nt], al[1], bh0, bh1);
                mma8(acc[0][nt], ah[0], bl0, bl1);
                mma8(acc[1][nt], ah[1], bl0, bl1);
            }
        }
    }

    // ---- per-pixel inverse norms (4-lane reduce over lk group) ----
    float qs[2][2];
#pragma unroll
    for (int mt = 0; mt < 2; ++mt)
#pragma unroll
        for (int hi = 0; hi < 2; ++hi) {
            float nr = nrm[mt][hi];
            nr += __shfl_xor_sync(0xFFFFFFFFu, nr, 1);
            nr += __shfl_xor_sync(0xFFFFFFFFu, nr, 2);
            qs[mt][hi] = 1.0f / fmaxf(sqrtf(nr), 1e-4f);
        }

    // ---- fused masked softmax + weighted sum + argmax ----
    float* cse = (float*)(sm + SM_CSE);
    float* csd = (float*)(sm + SM_CSD);
    float* cbv = (float*)(sm + SM_CBV);
    int*   cbn = (int*)  (sm + SM_CBN);
    const int nbase = widN * 128 + lk * 2;

#pragma unroll
    for (int mt = 0; mt < 2; ++mt)
#pragma unroll
        for (int hi = 0; hi < 2; ++hi) {
            const float sc = qs[mt][hi];
            float se = 0.f, sd = 0.f, bv = -3.0e38f;
            int bn = 1 << 30;
#pragma unroll
            for (int nt = 0; nt < 16; ++nt)
#pragma unroll
                for (int c2 = 0; c2 < 2; ++c2) {
                    const int n = nbase + nt * 8 + c2;
                    float mv = (sel_s[n] > 0.5f)
                             ? acc[mt][nt][hi * 2 + c2] * sc : -1.0e9f;
                    if (mv > bv) { bv = mv; bn = n; }
                    float e = __expf(mv);       // unshifted; mv <= 20
                    se += e;
                    sd += e * mv;
                }
#pragma unroll
            for (int off = 1; off <= 2; off <<= 1) {
                float ov = __shfl_xor_sync(0xFFFFFFFFu, bv, off);
                int   on = __shfl_xor_sync(0xFFFFFFFFu, bn, off);
                se += __shfl_xor_sync(0xFFFFFFFFu, se, off);
                sd += __shfl_xor_sync(0xFFFFFFFFu, sd, off);
                if (ov > bv || (ov == bv && on < bn)) { bv = ov; bn = on; }
            }
            const int pix = widM * 32 + mt * 16 + hi * 8 + lq;
            if (widN == 1 && lk == 0) {
                cse[pix] = se; csd[pix] = sd; cbv[pix] = bv; cbn[pix] = bn;
            }
            // stash for after-sync merge
            nrm[mt][hi] = se;  qs[mt][hi] = sd;
            acc[mt][0][hi] = bv; acc[mt][1][hi] = __int_as_float(bn);
        }
    __syncthreads();
    if (widN == 0 && lk == 0) {
#pragma unroll
        for (int mt = 0; mt < 2; ++mt)
#pragma unroll
            for (int hi = 0; hi < 2; ++hi) {
                const int pix = widM * 32 + mt * 16 + hi * 8 + lq;
                float se = nrm[mt][hi] + cse[pix];
                float sd = qs[mt][hi] + csd[pix];
                float bv = acc[mt][0][hi];
                int bn = __float_as_int(acc[mt][1][hi]);
                if (cbv[pix] > bv) { bv = cbv[pix]; bn = cbn[pix]; }
                out[m0 + pix]      = sd / se;
                out[HW + m0 + pix] = (float)bn;
            }
    }
}

// ---------------------------------------------------------------------------
extern "C" void kernel_launch(void* const* d_in, const int* in_sizes, int n_in,
                              void* d_out, int out_size) {
    const float* qry   = (const float*)d_in[0];
    const float* sup_x = (const float*)d_in[1];
    const float* sup_y = (const float*)d_in[2];
    const float* cal   = (const float*)d_in[4];
    float* out = (float*)d_out;

    cudaFuncSetAttribute(gemm_mma_kernel,
                         cudaFuncAttributeMaxDynamicSharedMemorySize, SMEM_BYTES);

    pool_kernel<<<C + 1, 256>>>(sup_x, sup_y);
    w1_kernel<<<C, 256>>>(cal);
    proto_kernel<<<C, 256>>>();
    gemm_mma_kernel<<<HW / BMPIX, 256, SMEM_BYTES>>>(qry, out);
}